// round 10
// baseline (speedup 1.0000x reference)
#include <cuda_runtime.h>

// Problem shape fixed by setup_inputs(): B=16, C=1024, H=W=32, NH=16.
#define B_  16
#define C_  1024
#define H_  32
#define W_  32
#define HW_ (H_*W_)
#define NH_ 16
#define P_  (H_*W_)       // 1024
#define N_  (P_+1)        // 1025
#define K_  10

// Scratch (__device__ globals; no allocations allowed)
__device__ float        g_cls[B_][P_];     // sum over heads of cls attn
__device__ float        g_slf[B_][P_];     // sum over heads of self attn
__device__ int          g_cpos[B_][K_];    // center positions (top-k)
__device__ int          g_nbr[B_][K_][8];  // clipped neighbor positions
__device__ unsigned int g_win[B_][K_];     // winner bitmask per slot

__constant__ int c_dy[8] = {-1,-1,-1, 0, 0, 1, 1, 1};
__constant__ int c_dx[8] = {-1, 0, 1,-1, 1,-1, 0, 1};

// ---------------------------------------------------------------------------
// Launch 1: pure bulk copy fm -> out. 128 MB of traffic, zero ALU overhead.
// Specials get overwritten later by suppress_kernel (same stream => ordered).
// ---------------------------------------------------------------------------
__global__ void __launch_bounds__(256) copy_kernel(const float4* __restrict__ in,
                                                   float4* __restrict__ out) {
    int i = blockIdx.x * 256 + threadIdx.x;
    out[i] = in[i];
}

// ---------------------------------------------------------------------------
// Launch 2: cls sums (coalesced row-0 reads) + zero the diag accumulator.
// ---------------------------------------------------------------------------
__global__ void __launch_bounds__(1024) cls_kernel(const float* __restrict__ attn) {
    int b = blockIdx.x, t = threadIdx.x;
    const float* base = attn + (size_t)b * NH_ * (size_t)N_ * N_ + 1 + t;
    float s = 0.f;
#pragma unroll
    for (int h = 0; h < NH_; h++)
        s += __ldg(base + (size_t)h * N_ * N_);
    g_cls[b][t] = s;
    g_slf[b][t] = 0.f;
}

// ---------------------------------------------------------------------------
// Launch 3: diagonal gather (measured 10.5us). One load + one spread atomic
// per thread. grid = 1024 blocks x 256 threads: block = (bh, quarter).
// ---------------------------------------------------------------------------
__global__ void __launch_bounds__(256) diag_kernel(const float* __restrict__ attn) {
    int g  = blockIdx.x;
    int bh = g >> 2;
    int q  = g & 3;
    int p  = q * 256 + threadIdx.x;
    int b  = bh >> 4;
    float v = __ldg(attn + (size_t)bh * N_ * N_ + (size_t)(1 + p) * (N_ + 1));
    atomicAdd(&g_slf[b][p], v);
}

// ---------------------------------------------------------------------------
// Launch 4: plan. Warp top-10 (registers only, no dynamic indexing) +
// parallel last-writer-wins winner bitmask. grid = B x 128 threads.
// ALL __syncthreads() at convergent scope (R9's divergent barriers hung).
// ratio = cls_sum / (slf_sum + 16e-8)  ==  (cls/16) / (slf/16 + 1e-8)
// ---------------------------------------------------------------------------
__global__ void __launch_bounds__(128) plan_kernel() {
    int b = blockIdx.x;
    int t = threadIdx.x;

    __shared__ int sh_sel[K_];
    __shared__ int sh_tgt[K_ * 8];

    if (t < K_) g_win[b][t] = 0u;

    if (t < 32) {
        int lane = t;
        unsigned long long key[32];
#pragma unroll
        for (int u = 0; u < 32; u++) {
            int p = u * 32 + lane;
            float rt = g_cls[b][p] / (g_slf[b][p] + 1.6e-7f);
            key[u] = ((unsigned long long)__float_as_uint(rt) << 32)
                   | (unsigned)(0xFFFFFFFFu - (unsigned)p);   // tie -> smaller index
        }
#pragma unroll
        for (int k = 0; k < K_; k++) {
            unsigned long long lm = 0ull;
#pragma unroll
            for (int u = 0; u < 32; u++)
                if (key[u] > lm) lm = key[u];
            unsigned long long wm = lm;
#pragma unroll
            for (int off = 16; off; off >>= 1) {
                unsigned long long o = __shfl_xor_sync(0xffffffffu, wm, off);
                if (o > wm) wm = o;
            }
#pragma unroll
            for (int u = 0; u < 32; u++)       // static-index removal (keys unique)
                if (key[u] == wm) key[u] = 0ull;
            if (lane == 0)
                sh_sel[k] = (int)(0xFFFFFFFFu - (unsigned)(wm & 0xFFFFFFFFull));
        }
    }
    __syncthreads();

    int q = -1;
    if (t < K_ * 8) {
        int i = t >> 3, j = t & 7;
        int sel = sh_sel[i];
        int r = sel >> 5, c = sel & 31;
        int y = r + c_dy[j]; y = y < 0 ? 0 : (y > H_ - 1 ? H_ - 1 : y);
        int x = c + c_dx[j]; x = x < 0 ? 0 : (x > W_ - 1 ? W_ - 1 : x);
        q = y * W_ + x;
        sh_tgt[t] = q;
        g_nbr[b][i][j] = q;
    }
    if (t < K_) g_cpos[b][t] = sh_sel[t];
    __syncthreads();                           // convergent

    if (t < K_ * 8) {
        int i = t >> 3, j = t & 7;
        // winner iff target is not any center AND no later slot claims it
        bool center = false;
#pragma unroll
        for (int m = 0; m < K_; m++)
            if (q == sh_sel[m]) center = true;
        bool later = false;
        for (int k2 = t + 1; k2 < K_ * 8; k2++)
            if (sh_tgt[k2] == q) later = true;
        if (!center && !later)
            atomicOr(&g_win[b][i], 1u << j);
    }
}

// ---------------------------------------------------------------------------
// Launch 5: fused stats + special-position writes (suppress).
// One block per (b,slot): 512 threads x 2 channels. Reads 9 positions/channel
// from ORIGINAL fm (kept in registers), block-reduces 17 sums, computes
// w/str, then immediately writes center wavg + winner columns into out.
// Winner sets are globally disjoint (last-writer-wins precomputed) and the
// copy kernel already wrote everything else => race-free, order-safe.
// ---------------------------------------------------------------------------
__global__ void __launch_bounds__(512) suppress_kernel(const float* __restrict__ fm,
                                                       float* __restrict__ out) {
    int blk = blockIdx.x;
    int b = blk / K_, i = blk % K_;
    int cpos = g_cpos[b][i];
    unsigned win = g_win[b][i];
    int np[8];
#pragma unroll
    for (int j = 0; j < 8; j++) np[j] = g_nbr[b][i][j];

    const float* f = fm  + (size_t)b * C_ * HW_;
    float*       o = out + (size_t)b * C_ * HW_;
    int t = threadIdx.x;

    float ov[2];
    float nb[8][2];
    float dot[8] = {0,0,0,0,0,0,0,0};
    float n2[8]  = {0,0,0,0,0,0,0,0};
    float o2 = 0.f;

#pragma unroll
    for (int u = 0; u < 2; u++) {
        int ch = t + u * 512;
        const float* fc = f + (size_t)ch * HW_;
        float v = fc[cpos];
        ov[u] = v;
        o2 += v * v;
#pragma unroll
        for (int j = 0; j < 8; j++) {
            float nv = fc[np[j]];
            nb[j][u] = nv;
            dot[j] += nv * v;
            n2[j]  += nv * nv;
        }
    }

    __shared__ float part[17][16];
    float vals[17];
    vals[0] = o2;
#pragma unroll
    for (int j = 0; j < 8; j++) { vals[1 + j] = dot[j]; vals[9 + j] = n2[j]; }
#pragma unroll
    for (int k = 0; k < 17; k++) {
        float v = vals[k];
#pragma unroll
        for (int off = 16; off; off >>= 1) v += __shfl_down_sync(0xffffffffu, v, off);
        if ((t & 31) == 0) part[k][t >> 5] = v;
    }
    __syncthreads();

    __shared__ float s_w[8], s_str[8];
    if (t < 32) {
        float sums[17];
#pragma unroll
        for (int k = 0; k < 17; k++) {
            float v = (t < 16) ? part[k][t] : 0.f;
#pragma unroll
            for (int off = 8; off; off >>= 1) v += __shfl_down_sync(0xffffffffu, v, off);
            sums[k] = v;   // valid on lane 0
        }
        if (t == 0) {
            float on = fmaxf(sqrtf(sums[0]), 1e-12f);
            float sim[8], z[8];
            float zmax = -1e30f;
#pragma unroll
            for (int j = 0; j < 8; j++) {
                float nn = fmaxf(sqrtf(sums[9 + j]), 1e-12f);
                sim[j] = sums[1 + j] / (nn * on);
                z[j] = fmaxf(1.f - sim[j], 0.f);
                zmax = fmaxf(zmax, z[j]);
            }
            float es = 0.f, e[8];
#pragma unroll
            for (int j = 0; j < 8; j++) { e[j] = expf(z[j] - zmax); es += e[j]; }
            float inv = 1.f / es;
#pragma unroll
            for (int j = 0; j < 8; j++) {
                s_w[j]   = e[j] * inv;
                s_str[j] = fminf(fmaxf(sim[j] * 0.1f, 0.f), 1.f);
            }
        }
    }
    __syncthreads();

    float w[8], str[8];
#pragma unroll
    for (int j = 0; j < 8; j++) { w[j] = s_w[j]; str[j] = s_str[j]; }

#pragma unroll
    for (int u = 0; u < 2; u++) {
        int ch = t + u * 512;
        float* oc = o + (size_t)ch * HW_;
        float wa = 0.f;
#pragma unroll
        for (int j = 0; j < 8; j++) wa += nb[j][u] * w[j];
        oc[cpos] = wa;                                    // center <- wavg
#pragma unroll
        for (int j = 0; j < 8; j++) {
            if ((win >> j) & 1u)
                oc[np[j]] = nb[j][u] - ov[u] * str[j];    // winner
        }
    }
}

// ---------------------------------------------------------------------------
extern "C" void kernel_launch(void* const* d_in, const int* in_sizes, int n_in,
                              void* d_out, int out_size) {
    const float* fm   = (const float*)d_in[0];
    const float* attn = (const float*)d_in[1];
    float* out = (float*)d_out;

    copy_kernel<<<(B_ * C_ * HW_) / 4 / 256, 256>>>((const float4*)fm, (float4*)out);
    cls_kernel<<<B_, 1024>>>(attn);
    diag_kernel<<<1024, 256>>>(attn);
    plan_kernel<<<B_, 128>>>();
    suppress_kernel<<<B_ * K_, 512>>>(fm, out);
}

// round 11
// speedup vs baseline: 1.1326x; 1.1326x over previous
#include <cuda_runtime.h>

// Problem shape fixed by setup_inputs(): B=16, C=1024, H=W=32, NH=16.
#define B_  16
#define C_  1024
#define H_  32
#define W_  32
#define HW_ (H_*W_)
#define NH_ 16
#define P_  (H_*W_)       // 1024
#define N_  (P_+1)        // 1025
#define K_  10

// Scratch (__device__ globals; no allocations allowed)
__device__ float        g_cls[B_][P_];     // sum over heads of cls attn
__device__ float        g_slf[B_][P_];     // sum over heads of self attn
__device__ int          g_cpos[B_][K_];    // center positions (top-k)
__device__ int          g_nbr[B_][K_][8];  // clipped neighbor positions
__device__ unsigned int g_win[B_][K_];     // winner bitmask per slot

__constant__ int c_dy[8] = {-1,-1,-1, 0, 0, 1, 1, 1};
__constant__ int c_dx[8] = {-1, 0, 1,-1, 1,-1, 0, 1};

// ---------------------------------------------------------------------------
// Launch 1: pure bulk copy fm -> out (roofline floor: 128 MB traffic).
// Specials overwritten later by suppress_kernel (same stream => ordered).
// ---------------------------------------------------------------------------
__global__ void __launch_bounds__(256) copy_kernel(const float4* __restrict__ in,
                                                   float4* __restrict__ out) {
    int i = blockIdx.x * 256 + threadIdx.x;
    out[i] = in[i];
}

// ---------------------------------------------------------------------------
// Launch 2: cls sums (coalesced row-0 reads) + zero the diag accumulator.
// ---------------------------------------------------------------------------
__global__ void __launch_bounds__(1024) cls_kernel(const float* __restrict__ attn) {
    int b = blockIdx.x, t = threadIdx.x;
    const float* base = attn + (size_t)b * NH_ * (size_t)N_ * N_ + 1 + t;
    float s = 0.f;
#pragma unroll
    for (int h = 0; h < NH_; h++)
        s += __ldg(base + (size_t)h * N_ * N_);
    g_cls[b][t] = s;
    g_slf[b][t] = 0.f;
}

// ---------------------------------------------------------------------------
// Launch 3: diagonal gather (measured 10.5us). One load + one spread atomic
// per thread. grid = 1024 blocks x 256 threads: block = (bh, quarter).
// ---------------------------------------------------------------------------
__global__ void __launch_bounds__(256) diag_kernel(const float* __restrict__ attn) {
    int g  = blockIdx.x;
    int bh = g >> 2;
    int q  = g & 3;
    int p  = q * 256 + threadIdx.x;
    int b  = bh >> 4;
    float v = __ldg(attn + (size_t)bh * N_ * N_ + (size_t)(1 + p) * (N_ + 1));
    atomicAdd(&g_slf[b][p], v);
}

// ---------------------------------------------------------------------------
// Launch 4: plan. TWO-STAGE top-10 (R10's 32-keys/lane spilled to local mem
// and serialized at 25.7us; 8 keys/lane = 16 regs stays in registers).
// Stage 1: each of 4 warps -> local top-10 of its 256 positions (shared).
// Stage 2: warp 0 -> global top-10 of the 40 candidates (2 keys/lane).
// Then parallel last-writer-wins winner bitmask. grid = B x 128.
// ratio = cls_sum / (slf_sum + 16e-8)  ==  (cls/16) / (slf/16 + 1e-8)
// ---------------------------------------------------------------------------
__global__ void __launch_bounds__(128) plan_kernel() {
    int b = blockIdx.x;
    int t = threadIdx.x;
    int w = t >> 5, lane = t & 31;

    __shared__ unsigned long long sh_cand[4 * K_];
    __shared__ int sh_sel[K_];
    __shared__ int sh_tgt[K_ * 8];

    if (t < K_) g_win[b][t] = 0u;

    // ---- Stage 1: per-warp local top-10 (8 keys/lane, registers only) ----
    {
        unsigned long long key[8];
#pragma unroll
        for (int u = 0; u < 8; u++) {
            int p = w * 256 + u * 32 + lane;
            float rt = g_cls[b][p] / (g_slf[b][p] + 1.6e-7f);
            // ratio >= 0 -> float bits monotonic as unsigned; tie -> smaller p
            key[u] = ((unsigned long long)__float_as_uint(rt) << 32)
                   | (unsigned)(0xFFFFFFFFu - (unsigned)p);
        }
#pragma unroll
        for (int k = 0; k < K_; k++) {
            unsigned long long lm = 0ull;
#pragma unroll
            for (int u = 0; u < 8; u++)
                if (key[u] > lm) lm = key[u];
            unsigned long long wm = lm;
#pragma unroll
            for (int off = 16; off; off >>= 1) {
                unsigned long long o = __shfl_xor_sync(0xffffffffu, wm, off);
                if (o > wm) wm = o;
            }
#pragma unroll
            for (int u = 0; u < 8; u++)        // static-index removal (keys unique)
                if (key[u] == wm) key[u] = 0ull;
            if (lane == 0) sh_cand[w * K_ + k] = wm;
        }
    }
    __syncthreads();

    // ---- Stage 2: warp 0 selects global top-10 from 40 candidates ----
    if (w == 0) {
        unsigned long long k0 = (lane < 4 * K_) ? sh_cand[lane] : 0ull;
        unsigned long long k1 = (lane + 32 < 4 * K_) ? sh_cand[lane + 32] : 0ull;
#pragma unroll
        for (int k = 0; k < K_; k++) {
            unsigned long long lm = k0 > k1 ? k0 : k1;
            unsigned long long wm = lm;
#pragma unroll
            for (int off = 16; off; off >>= 1) {
                unsigned long long o = __shfl_xor_sync(0xffffffffu, wm, off);
                if (o > wm) wm = o;
            }
            if (k0 == wm) k0 = 0ull;
            if (k1 == wm) k1 = 0ull;
            if (lane == 0)
                sh_sel[k] = (int)(0xFFFFFFFFu - (unsigned)(wm & 0xFFFFFFFFull));
        }
    }
    __syncthreads();

    // ---- Targets + winner mask (parallel, convergent barriers) ----
    int q = -1;
    if (t < K_ * 8) {
        int i = t >> 3, j = t & 7;
        int sel = sh_sel[i];
        int r = sel >> 5, c = sel & 31;
        int y = r + c_dy[j]; y = y < 0 ? 0 : (y > H_ - 1 ? H_ - 1 : y);
        int x = c + c_dx[j]; x = x < 0 ? 0 : (x > W_ - 1 ? W_ - 1 : x);
        q = y * W_ + x;
        sh_tgt[t] = q;
        g_nbr[b][i][j] = q;
    }
    if (t < K_) g_cpos[b][t] = sh_sel[t];
    __syncthreads();

    if (t < K_ * 8) {
        int i = t >> 3, j = t & 7;
        // winner iff target is not any center AND no later slot claims it
        bool center = false;
#pragma unroll
        for (int m = 0; m < K_; m++)
            if (q == sh_sel[m]) center = true;
        bool later = false;
        for (int k2 = t + 1; k2 < K_ * 8; k2++)
            if (sh_tgt[k2] == q) later = true;
        if (!center && !later)
            atomicOr(&g_win[b][i], 1u << j);
    }
}

// ---------------------------------------------------------------------------
// Launch 5: fused stats + special-position writes (suppress).
// One block per (b,slot): 512 threads x 2 channels. Reads 9 positions/channel
// from ORIGINAL fm (registers), block-reduces 17 sums, computes w/str, then
// writes center wavg + winner columns into out. Winner sets globally disjoint
// (last-writer-wins precomputed) => race-free, order-safe.
// ---------------------------------------------------------------------------
__global__ void __launch_bounds__(512) suppress_kernel(const float* __restrict__ fm,
                                                       float* __restrict__ out) {
    int blk = blockIdx.x;
    int b = blk / K_, i = blk % K_;
    int cpos = g_cpos[b][i];
    unsigned win = g_win[b][i];
    int np[8];
#pragma unroll
    for (int j = 0; j < 8; j++) np[j] = g_nbr[b][i][j];

    const float* f = fm  + (size_t)b * C_ * HW_;
    float*       o = out + (size_t)b * C_ * HW_;
    int t = threadIdx.x;

    float ov[2];
    float nb[8][2];
    float dot[8] = {0,0,0,0,0,0,0,0};
    float n2[8]  = {0,0,0,0,0,0,0,0};
    float o2 = 0.f;

#pragma unroll
    for (int u = 0; u < 2; u++) {
        int ch = t + u * 512;
        const float* fc = f + (size_t)ch * HW_;
        float v = fc[cpos];
        ov[u] = v;
        o2 += v * v;
#pragma unroll
        for (int j = 0; j < 8; j++) {
            float nv = fc[np[j]];
            nb[j][u] = nv;
            dot[j] += nv * v;
            n2[j]  += nv * nv;
        }
    }

    __shared__ float part[17][16];
    float vals[17];
    vals[0] = o2;
#pragma unroll
    for (int j = 0; j < 8; j++) { vals[1 + j] = dot[j]; vals[9 + j] = n2[j]; }
#pragma unroll
    for (int k = 0; k < 17; k++) {
        float v = vals[k];
#pragma unroll
        for (int off = 16; off; off >>= 1) v += __shfl_down_sync(0xffffffffu, v, off);
        if ((t & 31) == 0) part[k][t >> 5] = v;
    }
    __syncthreads();

    __shared__ float s_w[8], s_str[8];
    if (t < 32) {
        float sums[17];
#pragma unroll
        for (int k = 0; k < 17; k++) {
            float v = (t < 16) ? part[k][t] : 0.f;
#pragma unroll
            for (int off = 8; off; off >>= 1) v += __shfl_down_sync(0xffffffffu, v, off);
            sums[k] = v;   // valid on lane 0
        }
        if (t == 0) {
            float on = fmaxf(sqrtf(sums[0]), 1e-12f);
            float sim[8], z[8];
            float zmax = -1e30f;
#pragma unroll
            for (int j = 0; j < 8; j++) {
                float nn = fmaxf(sqrtf(sums[9 + j]), 1e-12f);
                sim[j] = sums[1 + j] / (nn * on);
                z[j] = fmaxf(1.f - sim[j], 0.f);
                zmax = fmaxf(zmax, z[j]);
            }
            float es = 0.f, e[8];
#pragma unroll
            for (int j = 0; j < 8; j++) { e[j] = expf(z[j] - zmax); es += e[j]; }
            float inv = 1.f / es;
#pragma unroll
            for (int j = 0; j < 8; j++) {
                s_w[j]   = e[j] * inv;
                s_str[j] = fminf(fmaxf(sim[j] * 0.1f, 0.f), 1.f);
            }
        }
    }
    __syncthreads();

    float w[8], str[8];
#pragma unroll
    for (int j = 0; j < 8; j++) { w[j] = s_w[j]; str[j] = s_str[j]; }

#pragma unroll
    for (int u = 0; u < 2; u++) {
        int ch = t + u * 512;
        float* oc = o + (size_t)ch * HW_;
        float wa = 0.f;
#pragma unroll
        for (int j = 0; j < 8; j++) wa += nb[j][u] * w[j];
        oc[cpos] = wa;                                    // center <- wavg
#pragma unroll
        for (int j = 0; j < 8; j++) {
            if ((win >> j) & 1u)
                oc[np[j]] = nb[j][u] - ov[u] * str[j];    // winner
        }
    }
}

// ---------------------------------------------------------------------------
extern "C" void kernel_launch(void* const* d_in, const int* in_sizes, int n_in,
                              void* d_out, int out_size) {
    const float* fm   = (const float*)d_in[0];
    const float* attn = (const float*)d_in[1];
    float* out = (float*)d_out;

    copy_kernel<<<(B_ * C_ * HW_) / 4 / 256, 256>>>((const float4*)fm, (float4*)out);
    cls_kernel<<<B_, 1024>>>(attn);
    diag_kernel<<<1024, 256>>>(attn);
    plan_kernel<<<B_, 128>>>();
    suppress_kernel<<<B_ * K_, 512>>>(fm, out);
}

// round 13
// speedup vs baseline: 1.1689x; 1.0320x over previous
#include <cuda_runtime.h>

// Problem shape fixed by setup_inputs(): B=16, C=1024, H=W=32, NH=16.
#define B_  16
#define C_  1024
#define H_  32
#define W_  32
#define HW_ (H_*W_)
#define NH_ 16
#define P_  (H_*W_)       // 1024
#define N_  (P_+1)        // 1025
#define K_  10

#define NB1_ 1184         // bulk kernel blocks
#define NT1_ 256

// Scratch (__device__ globals; no allocations allowed)
__device__ float        g_cls[B_][P_];        // sum over heads of cls attn
__device__ float        g_diag[B_*NH_][P_];   // per-head diagonal values (no atomics)
__device__ int          g_cpos[B_][K_];       // center positions (top-k)
__device__ int          g_nbr[B_][K_][8];     // clipped neighbor positions
__device__ unsigned int g_win[B_][K_];        // winner bitmask per slot

__constant__ int c_dy[8] = {-1,-1,-1, 0, 0, 1, 1, 1};
__constant__ int c_dx[8] = {-1, 0, 1,-1, 1,-1, 0, 1};

// ---------------------------------------------------------------------------
// Launch 1: bulk. Role-split blocks, NO inter-block dependencies:
//   blocks 0..15     : cls row sums for batch blk (coalesced)
//   blocks 16..1039  : one diag item each (bh, quarter) -> g_diag plain store
//   ALL blocks       : grid-stride float4 copy fm -> out
// cls/diag (~14us serial) hide under the ~24us bandwidth-bound copy.
// ---------------------------------------------------------------------------
__global__ void __launch_bounds__(NT1_) bulk_kernel(const float* __restrict__ fm,
                                                    const float* __restrict__ attn,
                                                    float* __restrict__ out) {
    int blk = blockIdx.x;
    int t   = threadIdx.x;

    if (blk < B_) {
        // cls sums for batch blk
        const float* base = attn + (size_t)blk * NH_ * N_ * N_;
#pragma unroll
        for (int u = 0; u < 4; u++) {
            int p = t + u * 256;
            float s = 0.f;
#pragma unroll
            for (int h = 0; h < NH_; h++)
                s += __ldg(base + (size_t)h * N_ * N_ + 1 + p);
            g_cls[blk][p] = s;
        }
    } else if (blk < B_ + B_ * NH_ * 4) {
        // one diag item: 256 scattered diagonal loads, plain store
        int item = blk - B_;
        int bh = item >> 2;
        int p  = (item & 3) * 256 + t;
        g_diag[bh][p] = __ldg(attn + (size_t)bh * N_ * N_ + (size_t)(1 + p) * (N_ + 1));
    }

    // grid-stride copy (all blocks)
    const float4* s4 = (const float4*)fm;
    float4*       d4 = (float4*)out;
    const int total  = (B_ * C_ * HW_) / 4;      // 4,194,304
    const int stride = NB1_ * NT1_;              // 303,104
    for (int i = blk * NT1_ + t; i < total; i += stride)
        d4[i] = s4[i];
}

// ---------------------------------------------------------------------------
// Launch 2: plan (R11's passing version; slf now summed from per-head g_diag).
// Two-stage top-10: 4 warps x 8 keys/lane (registers, no spill) -> 40
// candidates -> warp 0 global top-10. Then parallel last-writer-wins winner
// bitmask. grid = B x 128 threads.
// ratio = cls_sum / (slf_sum + 16e-8)  ==  (cls/16) / (slf/16 + 1e-8)
// ---------------------------------------------------------------------------
__global__ void __launch_bounds__(128) plan_kernel() {
    int b = blockIdx.x;
    int t = threadIdx.x;
    int w = t >> 5, lane = t & 31;

    __shared__ unsigned long long sh_cand[4 * K_];
    __shared__ int sh_sel[K_];
    __shared__ int sh_tgt[K_ * 8];

    if (t < K_) g_win[b][t] = 0u;

    // Stage 1: per-warp local top-10 (8 keys/lane)
    {
        unsigned long long key[8];
#pragma unroll
        for (int u = 0; u < 8; u++) {
            int p = w * 256 + u * 32 + lane;
            float slf = 0.f;
#pragma unroll
            for (int h = 0; h < NH_; h++)
                slf += g_diag[b * NH_ + h][p];
            float rt = g_cls[b][p] / (slf + 1.6e-7f);
            // ratio >= 0 -> float bits monotonic as unsigned; tie -> smaller p
            key[u] = ((unsigned long long)__float_as_uint(rt) << 32)
                   | (unsigned)(0xFFFFFFFFu - (unsigned)p);
        }
#pragma unroll
        for (int k = 0; k < K_; k++) {
            unsigned long long lm = 0ull;
#pragma unroll
            for (int u = 0; u < 8; u++)
                if (key[u] > lm) lm = key[u];
            unsigned long long wm = lm;
#pragma unroll
            for (int off = 16; off; off >>= 1) {
                unsigned long long o = __shfl_xor_sync(0xffffffffu, wm, off);
                if (o > wm) wm = o;
            }
#pragma unroll
            for (int u = 0; u < 8; u++)        // static-index removal (keys unique)
                if (key[u] == wm) key[u] = 0ull;
            if (lane == 0) sh_cand[w * K_ + k] = wm;
        }
    }
    __syncthreads();

    // Stage 2: warp 0 selects global top-10 from 40 candidates
    if (w == 0) {
        unsigned long long k0 = (lane < 4 * K_) ? sh_cand[lane] : 0ull;
        unsigned long long k1 = (lane + 32 < 4 * K_) ? sh_cand[lane + 32] : 0ull;
#pragma unroll
        for (int k = 0; k < K_; k++) {
            unsigned long long lm = k0 > k1 ? k0 : k1;
            unsigned long long wm = lm;
#pragma unroll
            for (int off = 16; off; off >>= 1) {
                unsigned long long o = __shfl_xor_sync(0xffffffffu, wm, off);
                if (o > wm) wm = o;
            }
            if (k0 == wm) k0 = 0ull;
            if (k1 == wm) k1 = 0ull;
            if (lane == 0)
                sh_sel[k] = (int)(0xFFFFFFFFu - (unsigned)(wm & 0xFFFFFFFFull));
        }
    }
    __syncthreads();

    // Targets + winner mask (parallel, convergent barriers)
    int q = -1;
    if (t < K_ * 8) {
        int i = t >> 3, j = t & 7;
        int sel = sh_sel[i];
        int r = sel >> 5, c = sel & 31;
        int y = r + c_dy[j]; y = y < 0 ? 0 : (y > H_ - 1 ? H_ - 1 : y);
        int x = c + c_dx[j]; x = x < 0 ? 0 : (x > W_ - 1 ? W_ - 1 : x);
        q = y * W_ + x;
        sh_tgt[t] = q;
        g_nbr[b][i][j] = q;
    }
    if (t < K_) g_cpos[b][t] = sh_sel[t];
    __syncthreads();

    if (t < K_ * 8) {
        int i = t >> 3, j = t & 7;
        // winner iff target is not any center AND no later slot claims it
        bool center = false;
#pragma unroll
        for (int m = 0; m < K_; m++)
            if (q == sh_sel[m]) center = true;
        bool later = false;
        for (int k2 = t + 1; k2 < K_ * 8; k2++)
            if (sh_tgt[k2] == q) later = true;
        if (!center && !later)
            atomicOr(&g_win[b][i], 1u << j);
    }
}

// ---------------------------------------------------------------------------
// Launch 3: fused stats + special-position writes (suppress). R11's passing
// version. One block per (b,slot): 512 threads x 2 channels. Winner sets
// globally disjoint (last-writer-wins precomputed) => race-free.
// ---------------------------------------------------------------------------
__global__ void __launch_bounds__(512) suppress_kernel(const float* __restrict__ fm,
                                                       float* __restrict__ out) {
    int blk = blockIdx.x;
    int b = blk / K_, i = blk % K_;
    int cpos = g_cpos[b][i];
    unsigned win = g_win[b][i];
    int np[8];
#pragma unroll
    for (int j = 0; j < 8; j++) np[j] = g_nbr[b][i][j];

    const float* f = fm  + (size_t)b * C_ * HW_;
    float*       o = out + (size_t)b * C_ * HW_;
    int t = threadIdx.x;

    float ov[2];
    float nb[8][2];
    float dot[8] = {0,0,0,0,0,0,0,0};
    float n2[8]  = {0,0,0,0,0,0,0,0};
    float o2 = 0.f;

#pragma unroll
    for (int u = 0; u < 2; u++) {
        int ch = t + u * 512;
        const float* fc = f + (size_t)ch * HW_;
        float v = fc[cpos];
        ov[u] = v;
        o2 += v * v;
#pragma unroll
        for (int j = 0; j < 8; j++) {
            float nv = fc[np[j]];
            nb[j][u] = nv;
            dot[j] += nv * v;
            n2[j]  += nv * nv;
        }
    }

    __shared__ float part[17][16];
    float vals[17];
    vals[0] = o2;
#pragma unroll
    for (int j = 0; j < 8; j++) { vals[1 + j] = dot[j]; vals[9 + j] = n2[j]; }
#pragma unroll
    for (int k = 0; k < 17; k++) {
        float v = vals[k];
#pragma unroll
        for (int off = 16; off; off >>= 1) v += __shfl_down_sync(0xffffffffu, v, off);
        if ((t & 31) == 0) part[k][t >> 5] = v;
    }
    __syncthreads();

    __shared__ float s_w[8], s_str[8];
    if (t < 32) {
        float sums[17];
#pragma unroll
        for (int k = 0; k < 17; k++) {
            float v = (t < 16) ? part[k][t] : 0.f;
#pragma unroll
            for (int off = 8; off; off >>= 1) v += __shfl_down_sync(0xffffffffu, v, off);
            sums[k] = v;   // valid on lane 0
        }
        if (t == 0) {
            float on = fmaxf(sqrtf(sums[0]), 1e-12f);
            float sim[8], z[8];
            float zmax = -1e30f;
#pragma unroll
            for (int j = 0; j < 8; j++) {
                float nn = fmaxf(sqrtf(sums[9 + j]), 1e-12f);
                sim[j] = sums[1 + j] / (nn * on);
                z[j] = fmaxf(1.f - sim[j], 0.f);
                zmax = fmaxf(zmax, z[j]);
            }
            float es = 0.f, e[8];
#pragma unroll
            for (int j = 0; j < 8; j++) { e[j] = expf(z[j] - zmax); es += e[j]; }
            float inv = 1.f / es;
#pragma unroll
            for (int j = 0; j < 8; j++) {
                s_w[j]   = e[j] * inv;
                s_str[j] = fminf(fmaxf(sim[j] * 0.1f, 0.f), 1.f);
            }
        }
    }
    __syncthreads();

    float w[8], str[8];
#pragma unroll
    for (int j = 0; j < 8; j++) { w[j] = s_w[j]; str[j] = s_str[j]; }

#pragma unroll
    for (int u = 0; u < 2; u++) {
        int ch = t + u * 512;
        float* oc = o + (size_t)ch * HW_;
        float wa = 0.f;
#pragma unroll
        for (int j = 0; j < 8; j++) wa += nb[j][u] * w[j];
        oc[cpos] = wa;                                    // center <- wavg
#pragma unroll
        for (int j = 0; j < 8; j++) {
            if ((win >> j) & 1u)
                oc[np[j]] = nb[j][u] - ov[u] * str[j];    // winner
        }
    }
}

// ---------------------------------------------------------------------------
extern "C" void kernel_launch(void* const* d_in, const int* in_sizes, int n_in,
                              void* d_out, int out_size) {
    const float* fm   = (const float*)d_in[0];
    const float* attn = (const float*)d_in[1];
    float* out = (float*)d_out;

    bulk_kernel<<<NB1_, NT1_>>>(fm, attn, out);
    plan_kernel<<<B_, 128>>>();
    suppress_kernel<<<B_ * K_, 512>>>(fm, out);
}